// round 1
// baseline (speedup 1.0000x reference)
#include <cuda_runtime.h>

// Problem constants (fixed by setup_inputs): x [8,4096,128] -> N=32768 rows, D=128; codebooks [4,1024,128]
#define RVQ_N   32768
#define RVQ_D   128
#define RVQ_K   1024
#define RVQ_M   4
#define ND_TOTAL (RVQ_N * RVQ_D)
#define TK      64            // codes per smem tile
#define NBLK    256           // level-kernel grid (128 rows per block)

// Scratch (device globals: allocation-free per harness rules)
static __device__ float  g_resid[ND_TOTAL];        // 16 MB residual buffer
static __device__ float  g_e2[RVQ_M * RVQ_K];      // per-code squared norms
static __device__ double g_lsum[RVQ_M * NBLK];     // per-(level,block) loss partials

// ---------------------------------------------------------------------------
// Precompute e2[k] = sum_d cb[k][d]^2 (fp32; order-insensitive at this scale)
// ---------------------------------------------------------------------------
__global__ void rvq_e2_kernel(const float* __restrict__ cb) {
    int k = blockIdx.x * blockDim.x + threadIdx.x;
    if (k < RVQ_M * RVQ_K) {
        const float* c = cb + (size_t)k * RVQ_D;
        float s = 0.f;
        #pragma unroll 8
        for (int i = 0; i < RVQ_D; i++)
            s = __fadd_rn(s, __fmul_rn(c[i], c[i]));
        g_e2[k] = s;
    }
}

// ---------------------------------------------------------------------------
// One RVQ level, fused: argmin over K codes + residual update + y accumulate
// + fp64 loss partial per block.
// Layout: 256 threads = 128 rows; thread pair (2i,2i+1) splits a row's 128
// dims into halves; codebook tiles of TK codes staged in smem (broadcast LDS).
// Numerics deliberately mirror the reference:
//   dist = fl( fl(r2 + e2_k) - 2*dot_k ), r2 = strict left-fold of 128 squares,
//   argmin = first (lowest) index via strict '<'.
// ---------------------------------------------------------------------------
__global__ void __launch_bounds__(256) rvq_level_kernel(
    const float* __restrict__ x,     // original input (used when lvl==0)
    const float* __restrict__ cb,    // codebooks base [M,K,D]
    float* __restrict__ y,           // output accumulator (q_sum)
    int lvl)
{
    __shared__ float  smc[TK * RVQ_D];   // 32 KB code tile
    __shared__ float  sme2[TK];
    __shared__ double sred[256];

    const int tid  = threadIdx.x;
    const int half = tid & 1;
    const int row  = blockIdx.x * 128 + (tid >> 1);

    const float* cbl = cb + (size_t)lvl * RVQ_K * RVQ_D;
    const float* src = (lvl == 0) ? x : (const float*)g_resid;

    // Load this thread's 64 residual values into registers
    float r[64];
    {
        const float4* rp = reinterpret_cast<const float4*>(src + (size_t)row * RVQ_D + half * 64);
        #pragma unroll
        for (int i = 0; i < 16; i++) {
            float4 v = rp[i];
            r[4*i+0] = v.x; r[4*i+1] = v.y; r[4*i+2] = v.z; r[4*i+3] = v.w;
        }
    }

    // r2 = strict sequential left-fold over all 128 elements (emulating a
    // scalar XLA reduce). half0 folds d=0..63; half1 continues the fold.
    float p = 0.f;
    #pragma unroll
    for (int i = 0; i < 64; i++) p = __fadd_rn(p, __fmul_rn(r[i], r[i]));
    float p_other = __shfl_xor_sync(0xffffffffu, p, 1);   // half1 receives half0's fold
    float t = p_other;
    #pragma unroll
    for (int i = 0; i < 64; i++) t = __fadd_rn(t, __fmul_rn(r[i], r[i]));
    float t_other = __shfl_xor_sync(0xffffffffu, t, 1);   // t valid on half1 only
    const float r2 = half ? t : t_other;

    // Argmin over K codes, tiled through smem
    float best = 3.4e38f;
    int   bidx = 0;

    for (int t0 = 0; t0 < RVQ_K; t0 += TK) {
        __syncthreads();
        {
            const float4* gsrc = reinterpret_cast<const float4*>(cbl + (size_t)t0 * RVQ_D);
            float4* sdst = reinterpret_cast<float4*>(smc);
            #pragma unroll
            for (int i = 0; i < (TK * RVQ_D / 4) / 256; i++)
                sdst[tid + i * 256] = gsrc[tid + i * 256];
            if (tid < TK) sme2[tid] = g_e2[lvl * RVQ_K + t0 + tid];
        }
        __syncthreads();

        #pragma unroll 2
        for (int c = 0; c < TK; ++c) {
            const float4* cp = reinterpret_cast<const float4*>(smc + c * RVQ_D + half * 64);
            float a0 = 0.f, a1 = 0.f, a2 = 0.f, a3 = 0.f;
            #pragma unroll
            for (int i = 0; i < 16; i++) {
                float4 v = cp[i];
                a0 = fmaf(r[4*i+0], v.x, a0);
                a1 = fmaf(r[4*i+1], v.y, a1);
                a2 = fmaf(r[4*i+2], v.z, a2);
                a3 = fmaf(r[4*i+3], v.w, a3);
            }
            float dot = (a0 + a1) + (a2 + a3);
            dot += __shfl_xor_sync(0xffffffffu, dot, 1);   // both halves get full dot
            float A    = __fadd_rn(r2, sme2[c]);           // fl(r2 + e2_k)
            float dist = __fadd_rn(A, -2.0f * dot);        // fl(A - 2*dot); -2*dot exact
            if (dist < best) { best = dist; bidx = t0 + c; }
        }
    }

    // Update: q gather, residual subtract, y accumulate, fp64 loss partial
    const float* q  = cbl + (size_t)bidx * RVQ_D + half * 64;
    float* ro = g_resid + (size_t)row * RVQ_D + half * 64;
    float* yp = y       + (size_t)row * RVQ_D + half * 64;
    double lsum = 0.0;
    #pragma unroll 4
    for (int i = 0; i < 64; i++) {
        float qi = q[i];
        float nr = __fadd_rn(r[i], -qi);      // residual - q (fp32, matches ref)
        ro[i] = nr;
        lsum  = fma((double)nr, (double)nr, lsum);
        yp[i] = (lvl == 0) ? qi : __fadd_rn(yp[i], qi);   // q_sum in fp32, ref op order
    }

    // Deterministic per-block loss reduction (fixed tree; no fp atomics)
    sred[tid] = lsum;
    __syncthreads();
    #pragma unroll
    for (int s2 = 128; s2 > 0; s2 >>= 1) {
        if (tid < s2) sred[tid] += sred[tid + s2];
        __syncthreads();
    }
    if (tid == 0) g_lsum[lvl * NBLK + blockIdx.x] = sred[0];
}

// ---------------------------------------------------------------------------
// Finalize: total_loss = 1.25 * (sum of all level residual^2 sums) / (N*D)
// (commitment and codebook losses are numerically identical; beta=0.25)
// Deterministic fixed-shape reduction of 1024 fp64 partials.
// ---------------------------------------------------------------------------
__global__ void rvq_finalize_kernel(float* __restrict__ out) {
    __shared__ double sred[256];
    int tid = threadIdx.x;
    double s = 0.0;
    #pragma unroll
    for (int i = 0; i < 4; i++) s += g_lsum[tid + i * 256];
    sred[tid] = s;
    __syncthreads();
    #pragma unroll
    for (int s2 = 128; s2 > 0; s2 >>= 1) {
        if (tid < s2) sred[tid] += sred[tid + s2];
        __syncthreads();
    }
    if (tid == 0) out[ND_TOTAL] = (float)(1.25 * sred[0] / (double)ND_TOTAL);
}

// ---------------------------------------------------------------------------
extern "C" void kernel_launch(void* const* d_in, const int* in_sizes, int n_in,
                              void* d_out, int out_size) {
    const float* x  = (const float*)d_in[0];   // [8,4096,128] fp32
    const float* cb = (const float*)d_in[1];   // [4,1024,128] fp32
    float* out = (float*)d_out;                // [N*D] y then [1] loss

    rvq_e2_kernel<<<(RVQ_M * RVQ_K + 255) / 256, 256>>>(cb);
    for (int lvl = 0; lvl < RVQ_M; lvl++)
        rvq_level_kernel<<<NBLK, 256>>>(x, cb, out, lvl);
    rvq_finalize_kernel<<<1, 256>>>(out);
    (void)in_sizes; (void)n_in; (void)out_size;
}

// round 3
// speedup vs baseline: 1.7289x; 1.7289x over previous
#include <cuda_runtime.h>

// Problem constants: x [8,4096,128] -> N=32768 rows, D=128; codebooks [4,1024,128]
#define RVQ_N   32768
#define RVQ_D   128
#define RVQ_K   1024
#define RVQ_M   4
#define ND_TOTAL (RVQ_N * RVQ_D)
#define NBLK    256            // level-kernel grid (128 rows per block)
#define ROWS_B  128            // rows per block
#define CTILE   256            // codes per tile
#define NTILES  (RVQ_K / CTILE)          // 4
#define KC      16                        // dims per k-chunk
#define NCHUNK  (RVQ_D / KC)              // 8
#define NGCHUNK (NTILES * NCHUNK)         // 32
#define SR_STRIDE   132        // padded row stride for transposed residual tile
#define SKEY_STRIDE 17

// Scratch (device globals: allocation-free per harness rules)
static __device__ float  g_resid[ND_TOTAL];          // 16 MB residual buffer
static __device__ float  g_e2[RVQ_M * RVQ_K];        // per-code squared norms
static __device__ float  g_cbT[RVQ_M * RVQ_D * RVQ_K]; // codebooks transposed [lvl][d][k], 2 MB
static __device__ double g_lsum[RVQ_M * NBLK];       // per-(level,block) loss partials

// ---------------------------------------------------------------------------
// e2[k] = sum_d cb[k][d]^2
// ---------------------------------------------------------------------------
__global__ void rvq_e2_kernel(const float* __restrict__ cb) {
    int k = blockIdx.x * blockDim.x + threadIdx.x;
    if (k < RVQ_M * RVQ_K) {
        const float* c = cb + (size_t)k * RVQ_D;
        float s = 0.f;
        #pragma unroll 8
        for (int i = 0; i < RVQ_D; i++)
            s = __fadd_rn(s, __fmul_rn(c[i], c[i]));
        g_e2[k] = s;
    }
}

// ---------------------------------------------------------------------------
// Transpose codebooks: g_cbT[lvl][d][k] = cb[lvl][k][d]   (2 MB, once/launch)
// ---------------------------------------------------------------------------
__global__ void rvq_tr_kernel(const float* __restrict__ cb) {
    int i = blockIdx.x * blockDim.x + threadIdx.x;   // input-coalesced
    if (i < RVQ_M * RVQ_K * RVQ_D) {
        int lvl = i >> 17;
        int r   = i & ((1 << 17) - 1);
        int k   = r >> 7;
        int d   = r & 127;
        g_cbT[lvl * (RVQ_D * RVQ_K) + d * RVQ_K + k] = cb[i];
    }
}

// ---------------------------------------------------------------------------
// One RVQ level: SGEMM-style dist compute (8 rows x 16 codes per thread),
// argmin via packed (dist_bits<<32)|idx keys, fused residual/y/loss epilogue.
// Numerics mirror the reference: dist = fl( fl(r2+e2) - 2*dot ), r2 = strict
// 128-element left-fold, argmin = first (lowest-index) min.
// ---------------------------------------------------------------------------
__global__ void __launch_bounds__(256, 1) rvq_level_v2(
    const float* __restrict__ x,
    const float* __restrict__ cb,
    float* __restrict__ y,
    int lvl)
{
    extern __shared__ unsigned char dynsmem[];
    float* s_r = (float*)dynsmem;                         // [128 dims][SR_STRIDE rows] transposed
    float* s_c = s_r + 128 * SR_STRIDE;                   // [2][KC][CTILE]
    float* sr2 = s_c + 2 * KC * CTILE;                    // [128]
    unsigned long long* skey = (unsigned long long*)(sr2 + 128);  // [128][SKEY_STRIDE]
    double* sredd = (double*)(skey + 128 * SKEY_STRIDE);  // [128]

    const int tid = threadIdx.x;
    const int tx  = tid & 15;      // code-dim thread coord (16 codes each)
    const int ty  = tid >> 4;      // row-dim thread coord (8 rows each)
    const int row0 = blockIdx.x * ROWS_B;

    const float* __restrict__ cbl = cb + (size_t)lvl * RVQ_K * RVQ_D;
    const float* __restrict__ cbT = g_cbT + (size_t)lvl * RVQ_D * RVQ_K;
    const float* __restrict__ src = (lvl == 0) ? x : (const float*)g_resid;

    // ---- load residual tile, transposed into smem ----
    {
        int row = tid & 127, half = tid >> 7;
        const float4* s4 = (const float4*)(src + (size_t)(row0 + row) * RVQ_D);
        #pragma unroll
        for (int i = 0; i < 16; i++) {
            int d4 = half * 16 + i;
            float4 v = s4[d4];
            float* p = s_r + (4 * d4) * SR_STRIDE + row;
            p[0]             = v.x;
            p[SR_STRIDE]     = v.y;
            p[2 * SR_STRIDE] = v.z;
            p[3 * SR_STRIDE] = v.w;
        }
    }
    __syncthreads();

    // ---- r2: strict sequential left-fold over 128 dims (matches reference) ----
    if (tid < 128) {
        float p = 0.f;
        #pragma unroll 8
        for (int d = 0; d < 128; d++) {
            float v = s_r[d * SR_STRIDE + tid];
            p = __fadd_rn(p, __fmul_rn(v, v));
        }
        sr2[tid] = p;
    }
    __syncthreads();

    float r2v[8];
    #pragma unroll
    for (int i = 0; i < 8; i++) r2v[i] = sr2[8 * ty + i];

    unsigned long long bk[8];
    #pragma unroll
    for (int i = 0; i < 8; i++) bk[i] = ~0ull;

    float acc[8][16];

    // ---- prefetch code chunk 0 (from transposed codebook; coalesced) ----
    const int kl = tid >> 6;    // 0..3: k sub-row within chunk
    const int c4 = tid & 63;    // 0..63: float4 column
    float4 pf0, pf1, pf2, pf3;
    {
        const float4* gp = (const float4*)(cbT + (size_t)kl * RVQ_K) + c4;
        pf0 = gp[0];
        pf1 = gp[4 * RVQ_K / 4];
        pf2 = gp[8 * RVQ_K / 4];
        pf3 = gp[12 * RVQ_K / 4];
    }

    // ---- main loop: 4 code tiles x 8 k-chunks, double-buffered ----
    #pragma unroll 1
    for (int g = 0; g < NGCHUNK; g++) {
        float* sc = s_c + (g & 1) * (KC * CTILE);
        // stage prefetched chunk
        ((float4*)(sc + (kl     ) * CTILE))[c4] = pf0;
        ((float4*)(sc + (kl +  4) * CTILE))[c4] = pf1;
        ((float4*)(sc + (kl +  8) * CTILE))[c4] = pf2;
        ((float4*)(sc + (kl + 12) * CTILE))[c4] = pf3;
        __syncthreads();

        if (g + 1 < NGCHUNK) {
            int t8 = (g + 1) >> 3, k8 = (g + 1) & 7;
            const float4* gp = (const float4*)(cbT + (size_t)(k8 * KC + kl) * RVQ_K + t8 * CTILE) + c4;
            pf0 = gp[0];
            pf1 = gp[4 * RVQ_K / 4];
            pf2 = gp[8 * RVQ_K / 4];
            pf3 = gp[12 * RVQ_K / 4];
        }

        if ((g & 7) == 0) {
            #pragma unroll
            for (int i = 0; i < 8; i++)
                #pragma unroll
                for (int j = 0; j < 16; j++) acc[i][j] = 0.f;
        }

        const int kc16 = (g & 7) * KC;
        #pragma unroll 4
        for (int k = 0; k < KC; k++) {
            const float4* rp = (const float4*)(s_r + (kc16 + k) * SR_STRIDE + 8 * ty);
            float4 ra = rp[0], rb = rp[1];
            const float4* cp = (const float4*)(sc + k * CTILE + 16 * tx);
            float4 ca = cp[0], cbv = cp[1], ccv = cp[2], cdv = cp[3];
            float rr[8] = {ra.x, ra.y, ra.z, ra.w, rb.x, rb.y, rb.z, rb.w};
            float cv[16] = {ca.x, ca.y, ca.z, ca.w, cbv.x, cbv.y, cbv.z, cbv.w,
                            ccv.x, ccv.y, ccv.z, ccv.w, cdv.x, cdv.y, cdv.z, cdv.w};
            #pragma unroll
            for (int i = 0; i < 8; i++)
                #pragma unroll
                for (int j = 0; j < 16; j++)
                    acc[i][j] = fmaf(rr[i], cv[j], acc[i][j]);
        }

        if ((g & 7) == 7) {   // end of a code tile: fold into running argmin
            int tile = g >> 3;
            int cbase = tile * CTILE + 16 * tx;
            const float4* ep = (const float4*)(g_e2 + lvl * RVQ_K + cbase);
            float4 e0 = ep[0], e1 = ep[1], e2v = ep[2], e3 = ep[3];
            float ev[16] = {e0.x, e0.y, e0.z, e0.w, e1.x, e1.y, e1.z, e1.w,
                            e2v.x, e2v.y, e2v.z, e2v.w, e3.x, e3.y, e3.z, e3.w};
            #pragma unroll
            for (int i = 0; i < 8; i++) {
                #pragma unroll
                for (int j = 0; j < 16; j++) {
                    float A    = __fadd_rn(r2v[i], ev[j]);          // fl(r2 + e2)
                    float dist = __fadd_rn(A, -2.0f * acc[i][j]);   // fl(A - 2*dot); dist > 0
                    unsigned long long key =
                        ((unsigned long long)__float_as_uint(dist) << 32) |
                        (unsigned)(cbase + j);
                    if (key < bk[i]) bk[i] = key;   // min dist, tie -> lowest index
                }
            }
        }
        __syncthreads();
    }

    // ---- cross-thread argmin per row ----
    #pragma unroll
    for (int i = 0; i < 8; i++) skey[(8 * ty + i) * SKEY_STRIDE + tx] = bk[i];
    __syncthreads();
    if (tid < 128) {
        unsigned long long b = skey[tid * SKEY_STRIDE];
        #pragma unroll
        for (int t = 1; t < 16; t++) {
            unsigned long long k2 = skey[tid * SKEY_STRIDE + t];
            if (k2 < b) b = k2;
        }
        skey[tid * SKEY_STRIDE] = b;
    }
    __syncthreads();

    // ---- epilogue: residual update, y accumulate, fp64 loss partial ----
    double ls = 0.0;
    if (tid < 128) {
        int row = tid, gr = row0 + row;
        int idx = (int)(skey[row * SKEY_STRIDE] & 0xffffffffull);
        const float4* q4 = (const float4*)(cbl + (size_t)idx * RVQ_D);
        float4* rout = (float4*)(g_resid + (size_t)gr * RVQ_D);
        float4* yp   = (float4*)(y + (size_t)gr * RVQ_D);
        #pragma unroll 4
        for (int d4 = 0; d4 < 32; d4++) {
            float4 q = q4[d4];
            float v0 = s_r[(4 * d4 + 0) * SR_STRIDE + row];
            float v1 = s_r[(4 * d4 + 1) * SR_STRIDE + row];
            float v2 = s_r[(4 * d4 + 2) * SR_STRIDE + row];
            float v3 = s_r[(4 * d4 + 3) * SR_STRIDE + row];
            float4 nr;
            nr.x = __fadd_rn(v0, -q.x);
            nr.y = __fadd_rn(v1, -q.y);
            nr.z = __fadd_rn(v2, -q.z);
            nr.w = __fadd_rn(v3, -q.w);
            rout[d4] = nr;
            ls = fma((double)nr.x, (double)nr.x, ls);
            ls = fma((double)nr.y, (double)nr.y, ls);
            ls = fma((double)nr.z, (double)nr.z, ls);
            ls = fma((double)nr.w, (double)nr.w, ls);
            float4 yv;
            if (lvl == 0) {
                yv = q;
            } else {
                yv = yp[d4];
                yv.x = __fadd_rn(yv.x, q.x);
                yv.y = __fadd_rn(yv.y, q.y);
                yv.z = __fadd_rn(yv.z, q.z);
                yv.w = __fadd_rn(yv.w, q.w);
            }
            yp[d4] = yv;
        }
    }
    if (tid < 128) sredd[tid] = ls;
    __syncthreads();
    #pragma unroll
    for (int s2 = 64; s2 > 0; s2 >>= 1) {
        if (tid < s2) sredd[tid] += sredd[tid + s2];
        __syncthreads();
    }
    if (tid == 0) g_lsum[lvl * NBLK + blockIdx.x] = sredd[0];
}

// ---------------------------------------------------------------------------
// total_loss = 1.25 * (sum of level residual^2 sums) / (N*D)
// ---------------------------------------------------------------------------
__global__ void rvq_finalize_kernel(float* __restrict__ out) {
    __shared__ double sred[256];
    int tid = threadIdx.x;
    double s = 0.0;
    #pragma unroll
    for (int i = 0; i < 4; i++) s += g_lsum[tid + i * 256];
    sred[tid] = s;
    __syncthreads();
    #pragma unroll
    for (int s2 = 128; s2 > 0; s2 >>= 1) {
        if (tid < s2) sred[tid] += sred[tid + s2];
        __syncthreads();
    }
    if (tid == 0) out[ND_TOTAL] = (float)(1.25 * sred[0] / (double)ND_TOTAL);
}

// ---------------------------------------------------------------------------
#define LEVEL_SMEM_BYTES ((128 * SR_STRIDE + 2 * KC * CTILE + 128) * 4 \
                          + 128 * SKEY_STRIDE * 8 + 128 * 8)

extern "C" void kernel_launch(void* const* d_in, const int* in_sizes, int n_in,
                              void* d_out, int out_size) {
    const float* x  = (const float*)d_in[0];   // [8,4096,128] fp32
    const float* cb = (const float*)d_in[1];   // [4,1024,128] fp32
    float* out = (float*)d_out;                // [N*D] y then [1] loss

    cudaFuncSetAttribute(rvq_level_v2,
                         cudaFuncAttributeMaxDynamicSharedMemorySize,
                         LEVEL_SMEM_BYTES);

    rvq_e2_kernel<<<(RVQ_M * RVQ_K + 255) / 256, 256>>>(cb);
    rvq_tr_kernel<<<(RVQ_M * RVQ_K * RVQ_D + 255) / 256, 256>>>(cb);
    for (int lvl = 0; lvl < RVQ_M; lvl++)
        rvq_level_v2<<<NBLK, 256, LEVEL_SMEM_BYTES>>>(x, cb, out, lvl);
    rvq_finalize_kernel<<<1, 256>>>(out);
    (void)in_sizes; (void)n_in; (void)out_size;
}

// round 6
// speedup vs baseline: 2.3739x; 1.3731x over previous
#include <cuda_runtime.h>

// Problem constants: x [8,4096,128] -> N=32768 rows, D=128; codebooks [4,1024,128]
#define RVQ_N   32768
#define RVQ_D   128
#define RVQ_K   1024
#define RVQ_M   4
#define ND_TOTAL (RVQ_N * RVQ_D)
#define NBLK    256            // level-kernel grid (128 rows per block)
#define ROWS_B  128            // rows per block
#define CTILE   128            // codes per tile
#define NTILES  (RVQ_K / CTILE)           // 8
#define KC      16                        // dims per k-chunk
#define NCHUNK  (RVQ_D / KC)              // 8
#define NGCHUNK (NTILES * NCHUNK)         // 64
#define SR_STRIDE   132        // padded row stride for transposed residual tile
#define SKEY_STRIDE 17

// Scratch (device globals: allocation-free per harness rules)
static __device__ float  g_resid[ND_TOTAL];            // 16 MB residual buffer
static __device__ float  g_e2[RVQ_M * RVQ_K];          // per-code squared norms
static __device__ float  g_cbT[RVQ_M * RVQ_D * RVQ_K]; // codebooks transposed [lvl][d][k]
static __device__ double g_lsum[RVQ_M * NBLK];         // per-(level,block) loss partials

// ---------------------------------------------------------------------------
// e2[k] = sum_d cb[k][d]^2
// ---------------------------------------------------------------------------
__global__ void rvq_e2_kernel(const float* __restrict__ cb) {
    int k = blockIdx.x * blockDim.x + threadIdx.x;
    if (k < RVQ_M * RVQ_K) {
        const float* c = cb + (size_t)k * RVQ_D;
        float s = 0.f;
        #pragma unroll 8
        for (int i = 0; i < RVQ_D; i++)
            s = __fadd_rn(s, __fmul_rn(c[i], c[i]));
        g_e2[k] = s;
    }
}

// ---------------------------------------------------------------------------
// Transpose codebooks: g_cbT[lvl][d][k] = cb[lvl][k][d]
// ---------------------------------------------------------------------------
__global__ void rvq_tr_kernel(const float* __restrict__ cb) {
    int i = blockIdx.x * blockDim.x + threadIdx.x;
    if (i < RVQ_M * RVQ_K * RVQ_D) {
        int lvl = i >> 17;
        int r   = i & ((1 << 17) - 1);
        int k   = r >> 7;
        int d   = r & 127;
        g_cbT[lvl * (RVQ_D * RVQ_K) + d * RVQ_K + k] = cb[i];
    }
}

// ---------------------------------------------------------------------------
// One RVQ level: SGEMM-style dist compute (8 rows x 8 codes per thread,
// 2 CTAs/SM for latency hiding), argmin via packed (dist<<32)|idx keys,
// fused residual/y/loss epilogue.
// Numerics mirror the reference: dist = fl( fl(r2+e2) - 2*dot ), r2 = strict
// 128-element left-fold, argmin = first (lowest-index) min.
// ---------------------------------------------------------------------------
__global__ void __launch_bounds__(256, 2) rvq_level_v3(
    const float* __restrict__ x,
    const float* __restrict__ cb,
    float* __restrict__ y,
    int lvl)
{
    extern __shared__ unsigned char dynsmem[];
    float* s_r = (float*)dynsmem;                         // [128 dims][SR_STRIDE rows]
    float* s_c = s_r + 128 * SR_STRIDE;                   // [2][KC][CTILE]
    float* sE2 = s_c + 2 * KC * CTILE;                    // [1024]
    float* sr2 = sE2 + RVQ_K;                             // [128]
    unsigned long long* skey = (unsigned long long*)(sr2 + 128);  // [128][SKEY_STRIDE]
    double* sredd = (double*)(skey + 128 * SKEY_STRIDE);  // [128]

    const int tid = threadIdx.x;
    const int tx  = tid & 15;      // code coord (8 codes each -> 128)
    const int ty  = tid >> 4;      // row coord  (8 rows each -> 128)
    const int row0 = blockIdx.x * ROWS_B;

    const float* __restrict__ cbl = cb + (size_t)lvl * RVQ_K * RVQ_D;
    const float* __restrict__ cbT = g_cbT + (size_t)lvl * RVQ_D * RVQ_K;
    const float* __restrict__ src = (lvl == 0) ? x : (const float*)g_resid;

    // ---- load residual tile, transposed into smem ----
    {
        int row = tid & 127, half = tid >> 7;
        const float4* s4 = (const float4*)(src + (size_t)(row0 + row) * RVQ_D);
        #pragma unroll
        for (int i = 0; i < 16; i++) {
            int d4 = half * 16 + i;
            float4 v = s4[d4];
            float* p = s_r + (4 * d4) * SR_STRIDE + row;
            p[0]             = v.x;
            p[SR_STRIDE]     = v.y;
            p[2 * SR_STRIDE] = v.z;
            p[3 * SR_STRIDE] = v.w;
        }
    }
    // stage e2 for this level
    #pragma unroll
    for (int it = 0; it < 4; it++)
        sE2[tid + (it << 8)] = g_e2[lvl * RVQ_K + tid + (it << 8)];
    __syncthreads();

    // ---- r2: strict sequential left-fold over 128 dims (matches reference) ----
    if (tid < 128) {
        float p = 0.f;
        #pragma unroll 8
        for (int d = 0; d < 128; d++) {
            float v = s_r[d * SR_STRIDE + tid];
            p = __fadd_rn(p, __fmul_rn(v, v));
        }
        sr2[tid] = p;
    }
    __syncthreads();

    float r2v[8];
    #pragma unroll
    for (int i = 0; i < 8; i++) r2v[i] = sr2[8 * ty + i];

    unsigned long long bk[8];
    #pragma unroll
    for (int i = 0; i < 8; i++) bk[i] = ~0ull;

    float acc[8][8];

    // ---- prefetch code chunk 0 (transposed codebook; coalesced) ----
    // chunk = 16 dims x 128 codes = 2048 floats; thread loads dims kl, kl+8
    const int kl = tid >> 5;     // 0..7
    const int c4 = tid & 31;     // float4 column (32*4 = 128 codes)
    float4 pf0, pf1;
    {
        const float4* gp = (const float4*)(cbT + (size_t)kl * RVQ_K) + c4;
        pf0 = gp[0];
        pf1 = gp[8 * RVQ_K / 4];
    }

    // ---- main loop: 8 code tiles x 8 k-chunks, double-buffered ----
    #pragma unroll 1
    for (int g = 0; g < NGCHUNK; g++) {
        float* sc = s_c + (g & 1) * (KC * CTILE);
        ((float4*)(sc + (kl    ) * CTILE))[c4] = pf0;
        ((float4*)(sc + (kl + 8) * CTILE))[c4] = pf1;
        __syncthreads();

        if (g + 1 < NGCHUNK) {
            int t8 = (g + 1) >> 3, k8 = (g + 1) & 7;
            const float4* gp = (const float4*)(cbT + (size_t)(k8 * KC + kl) * RVQ_K
                                               + t8 * CTILE) + c4;
            pf0 = gp[0];
            pf1 = gp[8 * RVQ_K / 4];
        }

        if ((g & 7) == 0) {
            #pragma unroll
            for (int i = 0; i < 8; i++)
                #pragma unroll
                for (int j = 0; j < 8; j++) acc[i][j] = 0.f;
        }

        const int kc16 = (g & 7) * KC;
        #pragma unroll 4
        for (int k = 0; k < KC; k++) {
            const float4* rp = (const float4*)(s_r + (kc16 + k) * SR_STRIDE + 8 * ty);
            float4 ra = rp[0], rb = rp[1];
            const float4* cp = (const float4*)(sc + k * CTILE + 8 * tx);
            float4 ca = cp[0], cb2 = cp[1];
            float rr[8] = {ra.x, ra.y, ra.z, ra.w, rb.x, rb.y, rb.z, rb.w};
            float cv[8] = {ca.x, ca.y, ca.z, ca.w, cb2.x, cb2.y, cb2.z, cb2.w};
            #pragma unroll
            for (int i = 0; i < 8; i++)
                #pragma unroll
                for (int j = 0; j < 8; j++)
                    acc[i][j] = fmaf(rr[i], cv[j], acc[i][j]);
        }

        if ((g & 7) == 7) {   // end of a code tile: fold into running argmin
            int tile = g >> 3;
            int cbase = tile * CTILE + 8 * tx;
            const float4* ep = (const float4*)(sE2 + cbase);
            float4 e0 = ep[0], e1 = ep[1];
            float ev[8] = {e0.x, e0.y, e0.z, e0.w, e1.x, e1.y, e1.z, e1.w};
            #pragma unroll
            for (int i = 0; i < 8; i++) {
                #pragma unroll
                for (int j = 0; j < 8; j++) {
                    float A    = __fadd_rn(r2v[i], ev[j]);          // fl(r2 + e2)
                    float dist = __fadd_rn(A, -2.0f * acc[i][j]);   // fl(A - 2*dot)
                    unsigned long long key =
                        ((unsigned long long)__float_as_uint(dist) << 32) |
                        (unsigned)(cbase + j);
                    if (key < bk[i]) bk[i] = key;   // min dist, tie -> lowest index
                }
            }
        }
        __syncthreads();
    }

    // ---- cross-thread argmin per row (16 tx threads per row) ----
    #pragma unroll
    for (int i = 0; i < 8; i++) skey[(8 * ty + i) * SKEY_STRIDE + tx] = bk[i];
    __syncthreads();
    if (tid < 128) {
        unsigned long long b = skey[tid * SKEY_STRIDE];
        #pragma unroll
        for (int t = 1; t < 16; t++) {
            unsigned long long k2 = skey[tid * SKEY_STRIDE + t];
            if (k2 < b) b = k2;
        }
        skey[tid * SKEY_STRIDE] = b;
    }
    __syncthreads();

    // ---- epilogue: residual update, y accumulate, fp64 loss partial ----
    double ls = 0.0;
    if (tid < 128) {
        int row = tid, gr = row0 + row;
        int idx = (int)(skey[row * SKEY_STRIDE] & 0xffffffffull);
        const float4* q4 = (const float4*)(cbl + (size_t)idx * RVQ_D);
        float4* rout = (float4*)(g_resid + (size_t)gr * RVQ_D);
        float4* yp   = (float4*)(y + (size_t)gr * RVQ_D);
        #pragma unroll 4
        for (int d4 = 0; d4 < 32; d4++) {
            float4 q = q4[d4];
            float v0 = s_r[(4 * d4 + 0) * SR_STRIDE + row];
            float v1 = s_r[(4 * d4 + 1) * SR_STRIDE + row];
            float v2 = s_r[(4 * d4 + 2) * SR_STRIDE + row];
            float v3 = s_r[(4 * d4 + 3) * SR_STRIDE + row];
            float4 nr;
            nr.x = __fadd_rn(v0, -q.x);
            nr.y = __fadd_rn(v1, -q.y);
            nr.z = __fadd_rn(v2, -q.z);
            nr.w = __fadd_rn(v3, -q.w);
            rout[d4] = nr;
            ls = fma((double)nr.x, (double)nr.x, ls);
            ls = fma((double)nr.y, (double)nr.y, ls);
            ls = fma((double)nr.z, (double)nr.z, ls);
            ls = fma((double)nr.w, (double)nr.w, ls);
            float4 yv;
            if (lvl == 0) {
                yv = q;
            } else {
                yv = yp[d4];
                yv.x = __fadd_rn(yv.x, q.x);
                yv.y = __fadd_rn(yv.y, q.y);
                yv.z = __fadd_rn(yv.z, q.z);
                yv.w = __fadd_rn(yv.w, q.w);
            }
            yp[d4] = yv;
        }
    }
    if (tid < 128) sredd[tid] = ls;
    __syncthreads();
    #pragma unroll
    for (int s2 = 64; s2 > 0; s2 >>= 1) {
        if (tid < s2) sredd[tid] += sredd[tid + s2];
        __syncthreads();
    }
    if (tid == 0) g_lsum[lvl * NBLK + blockIdx.x] = sredd[0];
}

// ---------------------------------------------------------------------------
// total_loss = 1.25 * (sum of level residual^2 sums) / (N*D)
// ---------------------------------------------------------------------------
__global__ void rvq_finalize_kernel(float* __restrict__ out) {
    __shared__ double sred[256];
    int tid = threadIdx.x;
    double s = 0.0;
    #pragma unroll
    for (int i = 0; i < 4; i++) s += g_lsum[tid + i * 256];
    sred[tid] = s;
    __syncthreads();
    #pragma unroll
    for (int s2 = 128; s2 > 0; s2 >>= 1) {
        if (tid < s2) sred[tid] += sred[tid + s2];
        __syncthreads();
    }
    if (tid == 0) out[ND_TOTAL] = (float)(1.25 * sred[0] / (double)ND_TOTAL);
}

// ---------------------------------------------------------------------------
#define LEVEL_SMEM_BYTES ((128 * SR_STRIDE + 2 * KC * CTILE + RVQ_K + 128) * 4 \
                          + 128 * SKEY_STRIDE * 8 + 128 * 8)

extern "C" void kernel_launch(void* const* d_in, const int* in_sizes, int n_in,
                              void* d_out, int out_size) {
    const float* x  = (const float*)d_in[0];   // [8,4096,128] fp32
    const float* cb = (const float*)d_in[1];   // [4,1024,128] fp32
    float* out = (float*)d_out;                // [N*D] y then [1] loss

    cudaFuncSetAttribute(rvq_level_v3,
                         cudaFuncAttributeMaxDynamicSharedMemorySize,
                         LEVEL_SMEM_BYTES);

    rvq_e2_kernel<<<(RVQ_M * RVQ_K + 255) / 256, 256>>>(cb);
    rvq_tr_kernel<<<(RVQ_M * RVQ_K * RVQ_D + 255) / 256, 256>>>(cb);
    for (int lvl = 0; lvl < RVQ_M; lvl++)
        rvq_level_v3<<<NBLK, 256, LEVEL_SMEM_BYTES>>>(x, cb, out, lvl);
    rvq_finalize_kernel<<<1, 256>>>(out);
    (void)in_sizes; (void)n_in; (void)out_size;
}